// round 9
// baseline (speedup 1.0000x reference)
#include <cuda_runtime.h>
#include <cuda_bf16.h>
#include <cstdint>

// Problem constants
#define N_NODES 100000
#define N_EDGES 1600000
#define D_FEAT  256
#define UNITS   128

// Static scratch (allocation-guard safe)
__device__ float g_h[(size_t)N_NODES * UNITS];                 // 51.2 MB
__device__ int g_count[N_NODES];
__device__ int g_offset[N_NODES + 1];
__device__ int g_cursor[N_NODES];
__device__ unsigned long long g_edges[N_EDGES];                // packed (val, src)

// ============================================================================
// Helpers
// ============================================================================
__device__ __forceinline__ uint32_t smem_u32(const void* p) {
    uint32_t a;
    asm("{ .reg .u64 t; cvta.to.shared.u64 t, %1; cvt.u32.u64 %0, t; }"
        : "=r"(a) : "l"(p));
    return a;
}

__device__ __forceinline__ uint32_t pk2(__nv_bfloat16 a, __nv_bfloat16 b) {
    uint16_t ua = *reinterpret_cast<uint16_t*>(&a);
    uint16_t ub = *reinterpret_cast<uint16_t*>(&b);
    return (uint32_t)ua | ((uint32_t)ub << 16);
}

#define LDSM_X4(r0, r1, r2, r3, addr) \
    asm volatile("ldmatrix.sync.aligned.m8n8.x4.shared.b16 {%0,%1,%2,%3}, [%4];" \
        : "=r"(r0), "=r"(r1), "=r"(r2), "=r"(r3) : "r"(addr))

#define MMA_BF16(c, a, b0, b1) \
    asm volatile("mma.sync.aligned.m16n8k16.row.col.f32.bf16.bf16.f32 " \
        "{%0,%1,%2,%3}, {%4,%5,%6,%7}, {%8,%9}, {%0,%1,%2,%3};" \
        : "+f"((c)[0]), "+f"((c)[1]), "+f"((c)[2]), "+f"((c)[3]) \
        : "r"((a)[0]), "r"((a)[1]), "r"((a)[2]), "r"((a)[3]), "r"(b0), "r"(b1))

// ============================================================================
// GEMM: h = x @ w, 2-way bf16 split on mma.sync (unchanged from R8)
// ============================================================================
#define TILE_M  128
#define NCHUNK  16
#define A_PITCH 48
#define B_PITCH 528
#define A_BUF_SZ (TILE_M * A_PITCH)
#define SMEM_A    0
#define SMEM_B_HI 24576
#define SMEM_B_LO (24576 + 67584)
#define SMEM_TOTAL (SMEM_B_LO + 67584)

__device__ __forceinline__ void cvt_store8(char* smem, int buf, int r, int kq,
                                           float4 v0, float4 v1) {
    float f[8] = {v0.x, v0.y, v0.z, v0.w, v1.x, v1.y, v1.z, v1.w};
    __nv_bfloat16 hi[8], lo[8];
#pragma unroll
    for (int e = 0; e < 8; e++) {
        hi[e] = __float2bfloat16(f[e]);
        lo[e] = __float2bfloat16(f[e] - __bfloat162float(hi[e]));
    }
    char* ph = smem + SMEM_A + buf * (2 * A_BUF_SZ) + r * A_PITCH + kq * 2;
    char* pl = ph + A_BUF_SZ;
    *(uint2*)(ph)     = make_uint2(pk2(hi[0], hi[1]), pk2(hi[2], hi[3]));
    *(uint2*)(ph + 8) = make_uint2(pk2(hi[4], hi[5]), pk2(hi[6], hi[7]));
    *(uint2*)(pl)     = make_uint2(pk2(lo[0], lo[1]), pk2(lo[2], lo[3]));
    *(uint2*)(pl + 8) = make_uint2(pk2(lo[4], lo[5]), pk2(lo[6], lo[7]));
}

__global__ __launch_bounds__(256, 1) void gemm_mma_kernel(const float* __restrict__ x,
                                                          const float* __restrict__ w,
                                                          float* __restrict__ h) {
    extern __shared__ char smem[];
    const uint32_t sb = smem_u32(smem);
    const int tid  = threadIdx.x;
    const int wid  = tid >> 5;
    const int lane = tid & 31;
    const int block_row = blockIdx.x * TILE_M;

    const int wm = (wid & 3) * 32;
    const int wn = (wid >> 2) * 64;

    for (int idx = tid; idx < D_FEAT * UNITS; idx += 256) {
        int k = idx >> 7, n = idx & 127;
        float v = __ldg(w + idx);
        __nv_bfloat16 hi = __float2bfloat16(v);
        __nv_bfloat16 lo = __float2bfloat16(v - __bfloat162float(hi));
        *(__nv_bfloat16*)(smem + SMEM_B_HI + n * B_PITCH + k * 2) = hi;
        *(__nv_bfloat16*)(smem + SMEM_B_LO + n * B_PITCH + k * 2) = lo;
    }

    const int pr = tid >> 1;
    const int pk = (tid & 1) * 8;
    const int grow = block_row + pr;
    const bool prow_ok = grow < N_NODES;
    const float* xrow = x + (size_t)(prow_ok ? grow : 0) * D_FEAT;

    {
        float4 v0 = make_float4(0, 0, 0, 0), v1 = v0;
        if (prow_ok) {
            v0 = *(const float4*)(xrow + pk);
            v1 = *(const float4*)(xrow + pk + 4);
        }
        cvt_store8(smem, 0, pr, pk, v0, v1);
    }
    __syncthreads();

    float acc[2][8][4];
#pragma unroll
    for (int i = 0; i < 2; i++)
#pragma unroll
        for (int j = 0; j < 8; j++)
#pragma unroll
            for (int q = 0; q < 4; q++) acc[i][j][q] = 0.0f;

    const uint32_t aRow = (uint32_t)(wm + (lane & 15)) * A_PITCH + ((lane >> 4) << 4);
    const uint32_t bRow = (uint32_t)(wn + (lane & 7) + ((lane >> 4) << 3)) * B_PITCH
                          + (((lane >> 3) & 1) << 4);

    for (int c = 0; c < NCHUNK; c++) {
        float4 v0 = make_float4(0, 0, 0, 0), v1 = v0;
        const bool pf = (c + 1 < NCHUNK);
        if (pf && prow_ok) {
            v0 = *(const float4*)(xrow + (c + 1) * 16 + pk);
            v1 = *(const float4*)(xrow + (c + 1) * 16 + pk + 4);
        }

        const uint32_t abase = sb + SMEM_A + (c & 1) * (2 * A_BUF_SZ) + aRow;
        uint32_t ah[2][4], al[2][4];
#pragma unroll
        for (int i = 0; i < 2; i++) {
            LDSM_X4(ah[i][0], ah[i][1], ah[i][2], ah[i][3], abase + i * 16 * A_PITCH);
            LDSM_X4(al[i][0], al[i][1], al[i][2], al[i][3],
                    abase + i * 16 * A_PITCH + A_BUF_SZ);
        }

        const uint32_t bbH = sb + SMEM_B_HI + bRow + c * 32;
        const uint32_t bbL = sb + SMEM_B_LO + bRow + c * 32;
#pragma unroll
        for (int jp = 0; jp < 4; jp++) {
            uint32_t bh[4], bl[4];
            LDSM_X4(bh[0], bh[1], bh[2], bh[3], bbH + jp * 16 * B_PITCH);
            LDSM_X4(bl[0], bl[1], bl[2], bl[3], bbL + jp * 16 * B_PITCH);
#pragma unroll
            for (int i = 0; i < 2; i++) {
                MMA_BF16(acc[i][2 * jp],     ah[i], bh[0], bh[1]);
                MMA_BF16(acc[i][2 * jp + 1], ah[i], bh[2], bh[3]);
                MMA_BF16(acc[i][2 * jp],     ah[i], bl[0], bl[1]);
                MMA_BF16(acc[i][2 * jp + 1], ah[i], bl[2], bl[3]);
                MMA_BF16(acc[i][2 * jp],     al[i], bh[0], bh[1]);
                MMA_BF16(acc[i][2 * jp + 1], al[i], bh[2], bh[3]);
            }
        }

        if (pf) cvt_store8(smem, (c + 1) & 1, pr, pk, v0, v1);
        __syncthreads();
    }

#pragma unroll
    for (int i = 0; i < 2; i++) {
#pragma unroll
        for (int j = 0; j < 8; j++) {
            int row0 = block_row + wm + i * 16 + (lane >> 2);
            int col  = wn + j * 8 + (lane & 3) * 2;
            if (row0 < N_NODES)
                *(float2*)(h + (size_t)row0 * UNITS + col) =
                    make_float2(acc[i][j][0], acc[i][j][1]);
            int row1 = row0 + 8;
            if (row1 < N_NODES)
                *(float2*)(h + (size_t)row1 * UNITS + col) =
                    make_float2(acc[i][j][2], acc[i][j][3]);
        }
    }
}

// ============================================================================
// CSR build: histogram -> scan -> bin
// ============================================================================
__global__ __launch_bounds__(256) void hist_kernel(const int* __restrict__ dst) {
    int i = blockIdx.x * blockDim.x + threadIdx.x;
    if (i < N_EDGES) atomicAdd(&g_count[dst[i]], 1);
}

__global__ __launch_bounds__(1024) void scan_kernel() {
    __shared__ int part[1024];
    const int tid = threadIdx.x;
    const int CHUNK = (N_NODES + 1023) / 1024;   // 98
    int begin = tid * CHUNK;
    int end = begin + CHUNK;
    if (end > N_NODES) end = N_NODES;
    if (begin > N_NODES) begin = N_NODES;

    int s = 0;
    for (int i = begin; i < end; i++) s += g_count[i];
    part[tid] = s;
    __syncthreads();

    // Kogge-Stone inclusive scan
    for (int off = 1; off < 1024; off <<= 1) {
        int v = (tid >= off) ? part[tid - off] : 0;
        __syncthreads();
        part[tid] += v;
        __syncthreads();
    }

    int run = (tid == 0) ? 0 : part[tid - 1];
    for (int i = begin; i < end; i++) {
        g_offset[i] = run;
        g_cursor[i] = run;
        run += g_count[i];
    }
    if (tid == 0) g_offset[N_NODES] = part[1023];
}

__global__ __launch_bounds__(256) void bin_kernel(const int* __restrict__ src,
                                                  const int* __restrict__ dst,
                                                  const float* __restrict__ vals) {
    int i = blockIdx.x * blockDim.x + threadIdx.x;
    if (i >= N_EDGES) return;
    int d = dst[i];
    int pos = atomicAdd(&g_cursor[d], 1);
    unsigned long long packed =
        ((unsigned long long)__float_as_uint(vals[i]) << 32) | (unsigned)src[i];
    g_edges[pos] = packed;
}

// ============================================================================
// Aggregate: one warp per dst node; register accumulation, single store.
// ============================================================================
__global__ __launch_bounds__(256) void aggregate_kernel(const float* __restrict__ h,
                                                        float* __restrict__ out) {
    const int node = (blockIdx.x * blockDim.x + threadIdx.x) >> 5;
    const int lane = threadIdx.x & 31;
    if (node >= N_NODES) return;

    const int start = g_offset[node];
    const int end   = g_offset[node + 1];

    float4 acc = make_float4(0.f, 0.f, 0.f, 0.f);

    int e = start;
    // 2-way unroll for memory-level parallelism on the gathers
    for (; e + 2 <= end; e += 2) {
        unsigned long long p0 = g_edges[e];
        unsigned long long p1 = g_edges[e + 1];
        int s0 = (int)(unsigned)p0;
        int s1 = (int)(unsigned)p1;
        float v0 = __uint_as_float((unsigned)(p0 >> 32));
        float v1 = __uint_as_float((unsigned)(p1 >> 32));
        float4 h0 = *(const float4*)(h + (size_t)s0 * UNITS + lane * 4);
        float4 h1 = *(const float4*)(h + (size_t)s1 * UNITS + lane * 4);
        acc.x += v0 * h0.x + v1 * h1.x;
        acc.y += v0 * h0.y + v1 * h1.y;
        acc.z += v0 * h0.z + v1 * h1.z;
        acc.w += v0 * h0.w + v1 * h1.w;
    }
    if (e < end) {
        unsigned long long p0 = g_edges[e];
        int s0 = (int)(unsigned)p0;
        float v0 = __uint_as_float((unsigned)(p0 >> 32));
        float4 h0 = *(const float4*)(h + (size_t)s0 * UNITS + lane * 4);
        acc.x += v0 * h0.x;
        acc.y += v0 * h0.y;
        acc.z += v0 * h0.z;
        acc.w += v0 * h0.w;
    }

    *(float4*)(out + (size_t)node * UNITS + lane * 4) = acc;
}

// ============================================================================
// Launch
// ============================================================================
extern "C" void kernel_launch(void* const* d_in, const int* in_sizes, int n_in,
                              void* d_out, int out_size) {
    const float* x    = (const float*)d_in[0];
    const float* w    = (const float*)d_in[1];
    const int*   src  = (const int*)d_in[2];
    const int*   dst  = (const int*)d_in[3];
    const float* vals = (const float*)d_in[4];
    float* out = (float*)d_out;

    float* h;
    cudaGetSymbolAddress((void**)&h, g_h);
    int* countp;
    cudaGetSymbolAddress((void**)&countp, g_count);

    // Zero histogram (400 KB)
    cudaMemsetAsync(countp, 0, N_NODES * sizeof(int), 0);

    // CSR build (independent of GEMM)
    hist_kernel<<<(N_EDGES + 255) / 256, 256>>>(dst);
    scan_kernel<<<1, 1024>>>();
    bin_kernel<<<(N_EDGES + 255) / 256, 256>>>(src, dst, vals);

    // GEMM: h = x @ w
    cudaFuncSetAttribute(gemm_mma_kernel,
                         cudaFuncAttributeMaxDynamicSharedMemorySize, SMEM_TOTAL);
    int gemm_blocks = (N_NODES + TILE_M - 1) / TILE_M;
    gemm_mma_kernel<<<gemm_blocks, 256, SMEM_TOTAL>>>(x, w, h);

    // Aggregate: writes every out row (zeros for isolated nodes) — no memset of out
    int agg_blocks = (N_NODES * 32 + 255) / 256;
    aggregate_kernel<<<agg_blocks, 256>>>(h, out);
}

// round 10
// speedup vs baseline: 1.3723x; 1.3723x over previous
#include <cuda_runtime.h>
#include <cuda_bf16.h>
#include <cstdint>

// Problem constants
#define N_NODES 100000
#define N_EDGES 1600000
#define D_FEAT  256
#define UNITS   128

// Static scratch
__device__ float g_h[(size_t)N_NODES * UNITS];                    // 51.2 MB
__device__ __nv_bfloat16 g_wh[UNITS * D_FEAT];                    // w hi, [n][k]
__device__ __nv_bfloat16 g_wl[UNITS * D_FEAT];                    // w lo, [n][k]

// ============================================================================
// Helpers
// ============================================================================
__device__ __forceinline__ uint32_t smem_u32(const void* p) {
    uint32_t a;
    asm("{ .reg .u64 t; cvta.to.shared.u64 t, %1; cvt.u32.u64 %0, t; }"
        : "=r"(a) : "l"(p));
    return a;
}

__device__ __forceinline__ uint32_t pk2(__nv_bfloat16 a, __nv_bfloat16 b) {
    uint16_t ua = *reinterpret_cast<uint16_t*>(&a);
    uint16_t ub = *reinterpret_cast<uint16_t*>(&b);
    return (uint32_t)ua | ((uint32_t)ub << 16);
}

#define LDSM_X4(r0, r1, r2, r3, addr) \
    asm volatile("ldmatrix.sync.aligned.m8n8.x4.shared.b16 {%0,%1,%2,%3}, [%4];" \
        : "=r"(r0), "=r"(r1), "=r"(r2), "=r"(r3) : "r"(addr))

#define MMA_BF16(c, a, b0, b1) \
    asm volatile("mma.sync.aligned.m16n8k16.row.col.f32.bf16.bf16.f32 " \
        "{%0,%1,%2,%3}, {%4,%5,%6,%7}, {%8,%9}, {%0,%1,%2,%3};" \
        : "+f"((c)[0]), "+f"((c)[1]), "+f"((c)[2]), "+f"((c)[3]) \
        : "r"((a)[0]), "r"((a)[1]), "r"((a)[2]), "r"((a)[3]), "r"(b0), "r"(b1))

// ============================================================================
// split_w: w[k][n] fp32 -> g_wh/g_wl[n][k] bf16 (hi/lo split), once.
// ============================================================================
__global__ __launch_bounds__(256) void split_w_kernel(const float* __restrict__ w) {
    int idx = blockIdx.x * blockDim.x + threadIdx.x;
    if (idx >= D_FEAT * UNITS) return;
    int k = idx >> 7, n = idx & 127;
    float v = w[idx];
    __nv_bfloat16 hi = __float2bfloat16(v);
    __nv_bfloat16 lo = __float2bfloat16(v - __bfloat162float(hi));
    g_wh[n * D_FEAT + k] = hi;
    g_wl[n * D_FEAT + k] = lo;
}

// ============================================================================
// GEMM: h = x @ w, 2-way bf16 split on mma.sync.
// CTA tile 128x128, 8 warps (4m x 2n), warp tile 32x64, K in 16 chunks of 16.
// Both A and B chunk-staged in smem (double-buffered, pitch 48) -> 48KB smem.
// ============================================================================
#define TILE_M  128
#define NCHUNK  16
#define PITCH   48        // 16 bf16 = 32B padded to 48B (conflict-free ldsm)
#define BUF_SZ  (128 * PITCH)                  // 6144 bytes (one hi or lo tile)
#define SMEM_A  0                              // 2 bufs x (hi+lo) = 24576
#define SMEM_B  24576                          // 2 bufs x (hi+lo) = 24576
#define SMEM_TOTAL 49152

__device__ __forceinline__ void cvt_store8(char* smem, int buf, int r, int kq,
                                           float4 v0, float4 v1) {
    float f[8] = {v0.x, v0.y, v0.z, v0.w, v1.x, v1.y, v1.z, v1.w};
    __nv_bfloat16 hi[8], lo[8];
#pragma unroll
    for (int e = 0; e < 8; e++) {
        hi[e] = __float2bfloat16(f[e]);
        lo[e] = __float2bfloat16(f[e] - __bfloat162float(hi[e]));
    }
    char* ph = smem + SMEM_A + buf * (2 * BUF_SZ) + r * PITCH + kq * 2;
    char* pl = ph + BUF_SZ;
    *(uint2*)(ph)     = make_uint2(pk2(hi[0], hi[1]), pk2(hi[2], hi[3]));
    *(uint2*)(ph + 8) = make_uint2(pk2(hi[4], hi[5]), pk2(hi[6], hi[7]));
    *(uint2*)(pl)     = make_uint2(pk2(lo[0], lo[1]), pk2(lo[2], lo[3]));
    *(uint2*)(pl + 8) = make_uint2(pk2(lo[4], lo[5]), pk2(lo[6], lo[7]));
}

__device__ __forceinline__ void b_store(char* smem, int buf, int n, int kq,
                                        uint4 bh, uint4 bl) {
    char* ph = smem + SMEM_B + buf * (2 * BUF_SZ) + n * PITCH + kq * 2;
    *(uint4*)(ph)          = bh;
    *(uint4*)(ph + BUF_SZ) = bl;
}

__global__ __launch_bounds__(256) void gemm_mma_kernel(const float* __restrict__ x,
                                                       float* __restrict__ h) {
    extern __shared__ char smem[];
    const uint32_t sb = smem_u32(smem);
    const int tid  = threadIdx.x;
    const int wid  = tid >> 5;
    const int lane = tid & 31;
    const int block_row = blockIdx.x * TILE_M;

    const int wm = (wid & 3) * 32;
    const int wn = (wid >> 2) * 64;

    // Per-thread staging assignment (row tid/2, 8 k-values at (tid&1)*8)
    const int pr = tid >> 1;
    const int pk = (tid & 1) * 8;
    const int grow = block_row + pr;
    const bool prow_ok = grow < N_NODES;
    const float* xrow = x + (size_t)(prow_ok ? grow : 0) * D_FEAT;
    const __nv_bfloat16* whrow = g_wh + pr * D_FEAT + pk;   // pr is also the n row
    const __nv_bfloat16* wlrow = g_wl + pr * D_FEAT + pk;

    // Preload chunk 0 into buf 0
    {
        float4 v0 = make_float4(0, 0, 0, 0), v1 = v0;
        if (prow_ok) {
            v0 = *(const float4*)(xrow + pk);
            v1 = *(const float4*)(xrow + pk + 4);
        }
        cvt_store8(smem, 0, pr, pk, v0, v1);
        uint4 bh = *(const uint4*)(whrow);
        uint4 bl = *(const uint4*)(wlrow);
        b_store(smem, 0, pr, pk, bh, bl);
    }
    __syncthreads();

    float acc[2][8][4];
#pragma unroll
    for (int i = 0; i < 2; i++)
#pragma unroll
        for (int j = 0; j < 8; j++)
#pragma unroll
            for (int q = 0; q < 4; q++) acc[i][j][q] = 0.0f;

    const uint32_t aRow = (uint32_t)(wm + (lane & 15)) * PITCH + ((lane >> 4) << 4);
    const uint32_t bRow = (uint32_t)(wn + (lane & 7) + ((lane >> 4) << 3)) * PITCH
                          + (((lane >> 3) & 1) << 4);

    for (int c = 0; c < NCHUNK; c++) {
        // Prefetch next chunk (A fp32, B bf16) into registers
        float4 v0 = make_float4(0, 0, 0, 0), v1 = v0;
        uint4 nbh = make_uint4(0, 0, 0, 0), nbl = nbh;
        const bool pf = (c + 1 < NCHUNK);
        if (pf) {
            if (prow_ok) {
                v0 = *(const float4*)(xrow + (c + 1) * 16 + pk);
                v1 = *(const float4*)(xrow + (c + 1) * 16 + pk + 4);
            }
            nbh = *(const uint4*)(whrow + (c + 1) * 16);
            nbl = *(const uint4*)(wlrow + (c + 1) * 16);
        }

        const uint32_t abase = sb + SMEM_A + (c & 1) * (2 * BUF_SZ) + aRow;
        uint32_t ah[2][4], al[2][4];
#pragma unroll
        for (int i = 0; i < 2; i++) {
            LDSM_X4(ah[i][0], ah[i][1], ah[i][2], ah[i][3], abase + i * 16 * PITCH);
            LDSM_X4(al[i][0], al[i][1], al[i][2], al[i][3],
                    abase + i * 16 * PITCH + BUF_SZ);
        }

        const uint32_t bbH = sb + SMEM_B + (c & 1) * (2 * BUF_SZ) + bRow;
        const uint32_t bbL = bbH + BUF_SZ;
#pragma unroll
        for (int jp = 0; jp < 4; jp++) {
            uint32_t bh[4], bl[4];
            LDSM_X4(bh[0], bh[1], bh[2], bh[3], bbH + jp * 16 * PITCH);
            LDSM_X4(bl[0], bl[1], bl[2], bl[3], bbL + jp * 16 * PITCH);
#pragma unroll
            for (int i = 0; i < 2; i++) {
                MMA_BF16(acc[i][2 * jp],     ah[i], bh[0], bh[1]);
                MMA_BF16(acc[i][2 * jp + 1], ah[i], bh[2], bh[3]);
                MMA_BF16(acc[i][2 * jp],     ah[i], bl[0], bl[1]);
                MMA_BF16(acc[i][2 * jp + 1], ah[i], bl[2], bl[3]);
                MMA_BF16(acc[i][2 * jp],     al[i], bh[0], bh[1]);
                MMA_BF16(acc[i][2 * jp + 1], al[i], bh[2], bh[3]);
            }
        }

        if (pf) {
            cvt_store8(smem, (c + 1) & 1, pr, pk, v0, v1);
            b_store(smem, (c + 1) & 1, pr, pk, nbh, nbl);
        }
        __syncthreads();
    }

    // Epilogue
#pragma unroll
    for (int i = 0; i < 2; i++) {
#pragma unroll
        for (int j = 0; j < 8; j++) {
            int row0 = block_row + wm + i * 16 + (lane >> 2);
            int col  = wn + j * 8 + (lane & 3) * 2;
            if (row0 < N_NODES)
                *(float2*)(h + (size_t)row0 * UNITS + col) =
                    make_float2(acc[i][j][0], acc[i][j][1]);
            int row1 = row0 + 8;
            if (row1 < N_NODES)
                *(float2*)(h + (size_t)row1 * UNITS + col) =
                    make_float2(acc[i][j][2], acc[i][j][3]);
        }
    }
}

// ----------------------------------------------------------------------------
// Scatter (R8 version): one warp per edge, float4 atomics.
// ----------------------------------------------------------------------------
__global__ __launch_bounds__(256) void scatter_kernel(const float* __restrict__ h,
                                                      const int* __restrict__ src,
                                                      const int* __restrict__ dst,
                                                      const float* __restrict__ vals,
                                                      float* __restrict__ out) {
    const int warp = (blockIdx.x * blockDim.x + threadIdx.x) >> 5;
    const int lane = threadIdx.x & 31;
    if (warp >= N_EDGES) return;

    const int s = src[warp];
    const int d = dst[warp];
    const float v = vals[warp];

    float4 hv = *(const float4*)(h + (size_t)s * UNITS + lane * 4);
    hv.x *= v; hv.y *= v; hv.z *= v; hv.w *= v;

    atomicAdd((float4*)(out + (size_t)d * UNITS + lane * 4), hv);
}

// ----------------------------------------------------------------------------
// Launch
// ----------------------------------------------------------------------------
extern "C" void kernel_launch(void* const* d_in, const int* in_sizes, int n_in,
                              void* d_out, int out_size) {
    const float* x    = (const float*)d_in[0];
    const float* w    = (const float*)d_in[1];
    const int*   src  = (const int*)d_in[2];
    const int*   dst  = (const int*)d_in[3];
    const float* vals = (const float*)d_in[4];
    float* out = (float*)d_out;

    cudaMemsetAsync(d_out, 0, (size_t)out_size * sizeof(float), 0);

    float* h;
    cudaGetSymbolAddress((void**)&h, g_h);

    // Split w once (32K elements)
    split_w_kernel<<<(D_FEAT * UNITS + 255) / 256, 256>>>(w);

    // GEMM: h = x @ w
    cudaFuncSetAttribute(gemm_mma_kernel,
                         cudaFuncAttributeMaxDynamicSharedMemorySize, SMEM_TOTAL);
    int gemm_blocks = (N_NODES + TILE_M - 1) / TILE_M;   // 782
    gemm_mma_kernel<<<gemm_blocks, 256, SMEM_TOTAL>>>(x, h);

    // Scatter
    int scatter_blocks = (N_EDGES + 7) / 8;
    scatter_kernel<<<scatter_blocks, 256>>>(h, src, dst, vals, out);
}